// round 1
// baseline (speedup 1.0000x reference)
#include <cuda_runtime.h>
#include <cstdint>
#include <math.h>

#define BB 32
#define NN 22743
#define CC 80
#define KK 2048
#define CAP 4096
#define MASKW (KK / 64)   // 32 words of 64 bits per row

// ---------------- device scratch (no allocations allowed) ----------------
__device__ float              g_mscore[BB * NN];          // masked score (-1 or score)
__device__ int                g_label[BB * NN];           // argmax class
__device__ unsigned long long g_keys[BB * CAP];           // compacted valid keys
__device__ int                g_vcount[BB];               // valid count per image
__device__ int                g_vc[BB];                   // min(V, K)
__device__ int                g_topidx[BB * KK];
__device__ float              g_topscore[BB * KK];
__device__ float              g_boxes[BB * KK * 4];       // clipped, unscaled
__device__ int                g_labtop[BB * KK];
__device__ unsigned           g_maxbits[BB];              // max box coord (float bits, >=0)
__device__ unsigned long long g_mask[(size_t)BB * KK * MASKW]; // 16 MB suppression bits

// ---------------- init ----------------
__global__ void init_kernel() {
    int t = threadIdx.x;
    if (t < BB) { g_vcount[t] = 0; g_maxbits[t] = 0u; }
}

// ---------------- K1: score/label + compact valid ----------------
// one warp per anchor; lanes cover the 80 class scores
__global__ void __launch_bounds__(256) score_kernel(const float* __restrict__ feat,
                                                    const float* __restrict__ pthresh) {
    int w    = (blockIdx.x * blockDim.x + threadIdx.x) >> 5;
    int lane = threadIdx.x & 31;
    if (w >= BB * NN) return;
    int b = w / NN;
    int i = w - b * NN;
    const float* row = feat + (size_t)w * 85;

    float v  = row[5 + lane];
    int   bi = lane;
    float v2 = row[5 + 32 + lane];
    if (v2 > v) { v = v2; bi = lane + 32; }
    if (lane < 16) {
        float v3 = row[5 + 64 + lane];
        if (v3 > v) { v = v3; bi = lane + 64; }
    }
    #pragma unroll
    for (int off = 16; off; off >>= 1) {
        float ov = __shfl_down_sync(0xffffffffu, v, off);
        int   oi = __shfl_down_sync(0xffffffffu, bi, off);
        if (ov > v || (ov == v && oi < bi)) { v = ov; bi = oi; }
    }
    if (lane == 0) {
        float rs     = row[4];
        float thresh = *pthresh;
        float sc     = __fmul_rn(v, rs);
        float m      = (sc >= thresh) ? sc : -1.0f;
        g_mscore[w] = m;
        g_label[w]  = bi;
        if (sc >= thresh) {
            int pos = atomicAdd(&g_vcount[b], 1);
            if (pos < CAP) {
                unsigned ord = __float_as_uint(m) ^ 0x80000000u; // positive floats
                g_keys[b * CAP + pos] =
                    ((unsigned long long)ord << 32) | (unsigned)(~(unsigned)i);
            }
        }
    }
}

// ---------------- K2: per-image sort of valid keys + filler slots ----------------
__global__ void __launch_bounds__(1024) topk_kernel(const float* __restrict__ pthresh) {
    __shared__ unsigned long long sk[CAP];
    __shared__ int sscan[1024];
    __shared__ int sbase;
    int b   = blockIdx.x;
    int tid = threadIdx.x;

    int V = g_vcount[b];
    if (V > CAP) V = CAP;
    for (int t = tid; t < CAP; t += 1024)
        sk[t] = (t < V) ? g_keys[b * CAP + t] : 0ull;
    __syncthreads();

    // bitonic sort, descending (valid keys have high bit set, pad=0 sinks)
    for (int k = 2; k <= CAP; k <<= 1) {
        for (int j = k >> 1; j > 0; j >>= 1) {
            for (int t = tid; t < CAP; t += 1024) {
                int l = t ^ j;
                if (l > t) {
                    bool desc = ((t & k) == 0);
                    unsigned long long a = sk[t], c = sk[l];
                    bool sw = desc ? (a < c) : (a > c);
                    if (sw) { sk[t] = c; sk[l] = a; }
                }
            }
            __syncthreads();
        }
    }

    int Vc = V < KK ? V : KK;
    if (tid == 0) g_vc[b] = Vc;
    for (int t = tid; t < Vc; t += 1024) {
        unsigned long long key = sk[t];
        g_topidx[b * KK + t]   = (int)(~(unsigned)key);
        g_topscore[b * KK + t] = __uint_as_float(((unsigned)(key >> 32)) ^ 0x80000000u);
    }
    __syncthreads();

    // fillers: first (K - Vc) invalid anchors in ascending index order, score = -1
    if (Vc < KK) {
        float thresh = *pthresh;
        int slots = KK - Vc;
        if (tid == 0) sbase = 0;
        __syncthreads();
        for (int t0 = 0; t0 < NN && sbase < slots; t0 += 1024) {
            int anchor = t0 + tid;
            int flag = (anchor < NN && g_mscore[b * NN + anchor] < thresh) ? 1 : 0;
            sscan[tid] = flag;
            __syncthreads();
            for (int off = 1; off < 1024; off <<= 1) {
                int add = (tid >= off) ? sscan[tid - off] : 0;
                __syncthreads();
                sscan[tid] += add;
                __syncthreads();
            }
            int pos = sbase + sscan[tid] - 1;
            if (flag && pos < slots) {
                g_topidx[b * KK + Vc + pos]   = anchor;
                g_topscore[b * KK + Vc + pos] = -1.0f;
            }
            __syncthreads();
            if (tid == 0) sbase += sscan[1023];
            __syncthreads();
        }
    }
}

// ---------------- K3: decode + clip + per-image max ----------------
__global__ void __launch_bounds__(256) decode_kernel(const float* __restrict__ feat,
                                                     const float* __restrict__ anchors,
                                                     const float* __restrict__ sizes) {
    int t = blockIdx.x * blockDim.x + threadIdx.x;
    if (t >= BB * KK) return;
    int b   = t / KK;
    int idx = g_topidx[t];
    const float* r = feat + ((size_t)b * NN + idx) * 85;
    const float* a = anchors + (size_t)idx * 5;
    float H = sizes[b * 2 + 0];
    float W = sizes[b * 2 + 1];

    float cx = __fmul_rn(__fadd_rn(r[0], a[0]), a[2]);
    float cy = __fmul_rn(__fadd_rn(r[1], a[1]), a[2]);
    float w  = __fmul_rn(a[3], expf(r[2]));
    float h  = __fmul_rn(a[4], expf(r[3]));
    float l  = __fsub_rn(cx, __fmul_rn(w, 0.5f));   // 0.5*w exact
    float tp = __fsub_rn(cy, __fmul_rn(h, 0.5f));
    float x2 = __fadd_rn(l, w);
    float y2 = __fadd_rn(tp, h);

    float Wm1 = __fsub_rn(W, 1.0f);
    float Hm1 = __fsub_rn(H, 1.0f);
    float b0 = fminf(fmaxf(l, 0.0f), Wm1);
    float b1 = fminf(fmaxf(tp, 0.0f), Hm1);
    float b2 = fminf(fmaxf(x2, 0.0f), Wm1);
    float b3 = fminf(fmaxf(y2, 0.0f), Hm1);

    g_boxes[t * 4 + 0] = b0;
    g_boxes[t * 4 + 1] = b1;
    g_boxes[t * 4 + 2] = b2;
    g_boxes[t * 4 + 3] = b3;
    g_labtop[t] = g_label[b * NN + idx];

    unsigned mb = __float_as_uint(fmaxf(fmaxf(b0, b1), fmaxf(b2, b3)));
    atomicMax(&g_maxbits[b], mb);   // all >= 0 -> bit compare == float compare
}

// ---------------- K4: suppression bitmask (upper triangle only) ----------------
__global__ void __launch_bounds__(64) mask_kernel(const float* __restrict__ pnms) {
    int b  = blockIdx.z;
    int Vc = g_vc[b];
    int rowbase = blockIdx.y * 64;
    int colbase = blockIdx.x * 64;
    if (rowbase >= Vc) return;

    __shared__ float4 cb[64];
    __shared__ float  ca[64];

    float maxb = __uint_as_float(g_maxbits[b]);
    float offm = __fadd_rn(maxb, 1.0f);
    float nth  = *pnms;
    int tid = threadIdx.x;

    int j = colbase + tid;
    if (j < Vc) {
        const float4 bx = ((const float4*)g_boxes)[b * KK + j];
        float off = __fmul_rn((float)g_labtop[b * KK + j], offm);
        float x1 = __fadd_rn(bx.x, off);
        float y1 = __fadd_rn(bx.y, off);
        float x2 = __fadd_rn(bx.z, off);
        float y2 = __fadd_rn(bx.w, off);
        cb[tid] = make_float4(x1, y1, x2, y2);
        ca[tid] = __fmul_rn(__fsub_rn(x2, x1), __fsub_rn(y2, y1));
    }
    __syncthreads();

    int i = rowbase + tid;
    if (i >= Vc) return;

    const float4 bx = ((const float4*)g_boxes)[b * KK + i];
    float off = __fmul_rn((float)g_labtop[b * KK + i], offm);
    float rx1 = __fadd_rn(bx.x, off);
    float ry1 = __fadd_rn(bx.y, off);
    float rx2 = __fadd_rn(bx.z, off);
    float ry2 = __fadd_rn(bx.w, off);
    float ra  = __fmul_rn(__fsub_rn(rx2, rx1), __fsub_rn(ry2, ry1));

    unsigned long long word = 0;
    int lim = Vc - colbase;
    if (lim > 64) lim = 64;
    for (int c = 0; c < lim; c++) {
        int jj = colbase + c;
        if (jj <= i) continue;
        float4 B = cb[c];
        float wdt = fmaxf(__fsub_rn(fminf(rx2, B.z), fmaxf(rx1, B.x)), 0.0f);
        float hgt = fmaxf(__fsub_rn(fminf(ry2, B.w), fmaxf(ry1, B.y)), 0.0f);
        float inter = __fmul_rn(wdt, hgt);
        float denom = __fadd_rn(__fsub_rn(__fadd_rn(ra, ca[c]), inter), 1e-9f);
        float iou = inter / denom;
        if (iou > nth) word |= 1ull << c;
    }
    g_mask[((size_t)b * KK + i) * MASKW + blockIdx.x] = word;
}

// ---------------- K5: greedy scan (1 warp) + final outputs ----------------
__global__ void __launch_bounds__(256) nms_out_kernel(const float* __restrict__ sizes,
                                                      const float* __restrict__ sizes_ori,
                                                      float* __restrict__ out) {
    __shared__ unsigned long long srem[MASKW];
    int b = blockIdx.x, tid = threadIdx.x;
    int Vc = g_vc[b];

    if (tid < 32) {
        unsigned long long rem = 0;
        for (int i = 0; i < Vc; i++) {
            unsigned long long w = __shfl_sync(0xffffffffu, rem, i >> 6);
            if (!((w >> (i & 63)) & 1ull)) {
                rem |= g_mask[((size_t)b * KK + i) * MASKW + tid];
            }
        }
        srem[tid] = rem;
    }
    __syncthreads();

    float scale = sizes_ori[b * 2] / sizes[b * 2];
    const size_t OB = 0;
    const size_t OS = (size_t)BB * KK * 4;
    const size_t OL = OS + (size_t)BB * KK;
    const size_t OK = OL + (size_t)BB * KK;

    for (int k = tid; k < KK; k += blockDim.x) {
        bool valid = k < Vc;
        bool kept  = valid && !((srem[k >> 6] >> (k & 63)) & 1ull);
        out[OS + (size_t)b * KK + k] = g_topscore[b * KK + k];
        out[OL + (size_t)b * KK + k] = (float)g_labtop[b * KK + k];
        out[OK + (size_t)b * KK + k] = kept ? 1.0f : 0.0f;
        #pragma unroll
        for (int c = 0; c < 4; c++)
            out[OB + ((size_t)b * KK + k) * 4 + c] =
                __fmul_rn(g_boxes[(b * KK + k) * 4 + c], scale);
    }
}

// ---------------- launcher ----------------
extern "C" void kernel_launch(void* const* d_in, const int* in_sizes, int n_in,
                              void* d_out, int out_size) {
    const float* feat      = (const float*)d_in[0];
    const float* anchors   = (const float*)d_in[1];
    const float* sizes     = (const float*)d_in[2];
    const float* sizes_ori = (const float*)d_in[3];
    const float* pthresh   = (const float*)d_in[4];
    const float* pnms      = (const float*)d_in[5];
    float* out = (float*)d_out;

    init_kernel<<<1, BB>>>();
    score_kernel<<<(BB * NN + 7) / 8, 256>>>(feat, pthresh);
    topk_kernel<<<BB, 1024>>>(pthresh);
    decode_kernel<<<(BB * KK + 255) / 256, 256>>>(feat, anchors, sizes);
    dim3 mg(MASKW, MASKW, BB);
    mask_kernel<<<mg, 64>>>(pnms);
    nms_out_kernel<<<BB, 256>>>(sizes, sizes_ori, out);
}